// round 13
// baseline (speedup 1.0000x reference)
#include <cuda_runtime.h>

// out[b, :] = table_bits[idx(b), :],  idx(b) = sum_k idx_bits[b,k] << (5-k)
// Table values are 0/1 pulses -> packed ONCE into 64-bit masks, stored
// PRE-REVERSED: g2[v] = mask of table row rev6(v). Persistent single-wave
// grid (1184 blocks = 148 SMs x 8 blocks); each warp grid-strides over
// 16-row chunks using R7's interleaved {4x index, 4x LDG.64, 4x expand+STG}.

#define BATCH   262144
#define THREADS 256
#define WARPS_PER_BLOCK (THREADS / 32)
#define GRID    1184                               // 148 SMs x 8 resident blocks
#define TOTAL_WARPS (GRID * WARPS_PER_BLOCK)       // 9472
#define CHUNKS  (BATCH / 16)                       // 16384 chunks of 16 rows

// g2[v] = mask of table row rev6(v); column c (0..63) at bit (63 - c).
__device__ unsigned long long g2[64];

__global__ void build_masks_kernel(const float* __restrict__ table)
{
    int w    = threadIdx.x >> 5;            // 0..15 -> rows w, w+16, w+32, w+48
    int lane = threadIdx.x & 31;
    #pragma unroll
    for (int t = 0; t < 4; t++) {
        int row = w + t * 16;
        float v0 = table[row * 64 + lane];        // cols 0..31
        float v1 = table[row * 64 + 32 + lane];   // cols 32..63
        unsigned hi = __brev(__ballot_sync(0xFFFFFFFFu, v0 > 0.5f));
        unsigned lo = __brev(__ballot_sync(0xFFFFFFFFu, v1 > 0.5f));
        if (lane == 0) {
            int v = (int)(__brev((unsigned)row) >> 26);   // rev6(row)
            g2[v] = ((unsigned long long)hi << 32) | (unsigned long long)lo;
        }
    }
}

__device__ __forceinline__ float bit_to_1f(unsigned nib, int k)
{
    // nibble bit (3-k) -> 0.0f / 1.0f  (1.0f = 0x3F800000)
    return __int_as_float(((int)(nib << (28 + k)) >> 31) & 0x3F800000);
}

__global__ __launch_bounds__(THREADS, 8)
void spike_lookup_kernel(const int* __restrict__ bits,    // BATCH*6
                         float4*    __restrict__ out4)    // BATCH*16
{
    const int lane  = threadIdx.x & 31;
    const int gwarp = blockIdx.x * WARPS_PER_BLOCK + (threadIdx.x >> 5);

    const int j    = lane & 15;        // float4 column within the 64-float row
    const int half = lane >> 4;        // row parity within the pair
    const int s    = 60 - 4 * j;       // cols 4j..4j+3 -> nibble bits 3..0
    const int hb   = 6 * half;         // bit offset delta for odd rows

    for (int c = gwarp; c < CHUNKS; c += TOTAL_WARPS) {
        // 16 rows * 6 ints = 96 ints, fully coalesced.
        const int* __restrict__ p = bits + c * 96;
        unsigned c0 = __ballot_sync(0xFFFFFFFFu, p[lane]      != 0);
        unsigned c1 = __ballot_sync(0xFFFFFFFFu, p[lane + 32] != 0);
        unsigned c2 = __ballot_sync(0xFFFFFFFFu, p[lane + 64] != 0);

        float4* __restrict__ dst = out4 + (long long)c * 256 + lane;

        #pragma unroll
        for (int g = 0; g < 2; g++) {
            // ---- 4 window extractions (table pre-reversed: raw index) ----
            unsigned idxv[4];
            #pragma unroll
            for (int i = 0; i < 4; i++) {
                int sh = 12 * (g * 4 + i) + hb;          // 0..90
                unsigned lo = (sh < 32) ? c0 : (sh < 64) ? c1 : c2;
                unsigned hi = (sh < 32) ? c1 : (sh < 64) ? c2 : 0u;
                idxv[i] = __funnelshift_r(lo, hi, sh) & 63u;
            }

            // ---- 4 broadcast mask loads (L1-hot) ----
            unsigned long long m[4];
            #pragma unroll
            for (int i = 0; i < 4; i++)
                m[i] = __ldg(&g2[idxv[i]]);

            // ---- 4 expands + contiguous STG.128 (512B per warp) ----
            #pragma unroll
            for (int i = 0; i < 4; i++) {
                unsigned nib = (unsigned)(m[i] >> s) & 0xFu;
                float4 v;
                v.x = bit_to_1f(nib, 0);
                v.y = bit_to_1f(nib, 1);
                v.z = bit_to_1f(nib, 2);
                v.w = bit_to_1f(nib, 3);
                dst[(g * 4 + i) * 32] = v;
            }
        }
    }
}

extern "C" void kernel_launch(void* const* d_in, const int* in_sizes, int n_in,
                              void* d_out, int out_size)
{
    const float* table = (const float*)d_in[0];
    const int*   bits  = (const int*)d_in[1];
    float4*      out4  = (float4*)d_out;

    build_masks_kernel<<<1, 512>>>(table);            // 16 warps x 4 rows
    spike_lookup_kernel<<<GRID, THREADS>>>(bits, out4);
}

// round 14
// speedup vs baseline: 1.1425x; 1.1425x over previous
#include <cuda_runtime.h>

// out[b, :] = table_bits[idx(b), :],  idx(b) = sum_k idx_bits[b,k] << (5-k)
// Table values are 0/1 pulses -> packed once into 64-bit masks (build kernel).
// Main kernel = R7's best-measured schedule + streaming cache hints:
// __ldcs on the bits stream, __stcs on the output stream (both touched once).

#define BATCH   262144
#define THREADS 256
#define ROWS_PER_WARP 16
#define GRID (BATCH / (ROWS_PER_WARP * (THREADS / 32)))   // 2048 blocks

// Mask for table row r: column c (0..63) lives at bit (63 - c).
__device__ unsigned long long g_masks[64];

__global__ void build_masks_kernel(const float* __restrict__ table)
{
    int w    = (blockIdx.x * blockDim.x + threadIdx.x) >> 5;   // 0..63 table row
    int lane = threadIdx.x & 31;
    float v0 = table[w * 64 + lane];        // cols 0..31
    float v1 = table[w * 64 + 32 + lane];   // cols 32..63
    unsigned hi = __brev(__ballot_sync(0xFFFFFFFFu, v0 > 0.5f)); // col c -> bit 31-c
    unsigned lo = __brev(__ballot_sync(0xFFFFFFFFu, v1 > 0.5f));
    if (lane == 0)
        g_masks[w] = ((unsigned long long)hi << 32) | (unsigned long long)lo;
}

__device__ __forceinline__ float bit_to_1f(unsigned nib, int k)
{
    // nibble bit (3-k) -> 0.0f / 1.0f  (1.0f = 0x3F800000)
    return __int_as_float(((int)(nib << (28 + k)) >> 31) & 0x3F800000);
}

__global__ __launch_bounds__(THREADS)
void spike_lookup_kernel(const int* __restrict__ bits,    // BATCH*6
                         float4*    __restrict__ out4)    // BATCH*16
{
    const int lane  = threadIdx.x & 31;
    const int gwarp = blockIdx.x * (THREADS / 32) + (threadIdx.x >> 5);

    // 16 rows * 6 ints = 96 ints, fully coalesced; streaming (touched once).
    const int* __restrict__ p = bits + gwarp * 96;
    unsigned b0 = __ballot_sync(0xFFFFFFFFu, __ldcs(&p[lane])      != 0);
    unsigned b1 = __ballot_sync(0xFFFFFFFFu, __ldcs(&p[lane + 32]) != 0);
    unsigned b2 = __ballot_sync(0xFFFFFFFFu, __ldcs(&p[lane + 64]) != 0);

    unsigned long long u01 = (unsigned long long)b0 | ((unsigned long long)b1 << 32);
    unsigned long long u12 = (unsigned long long)b1 | ((unsigned long long)b2 << 32);

    const int j    = lane & 15;        // float4 column within the 64-float row
    const int half = lane >> 4;        // row parity within the pair
    const int s    = 60 - 4 * j;       // cols 4j..4j+3 -> nibble bits 3..0

    float4* __restrict__ dst = out4 + (long long)gwarp * 256 + lane;

    #pragma unroll
    for (int g = 0; g < 2; g++) {
        float4 v[4];
        #pragma unroll
        for (int i = 0; i < 4; i++) {
            int r  = 2 * (g * 4 + i) + half;          // local row 0..15
            int sh = 6 * r;
            unsigned vb = (r < 10) ? (unsigned)(u01 >> sh)
                                   : (unsigned)(u12 >> (sh - 32));
            int idx = (int)(__brev(vb & 63u) >> 26);  // k=0 is MSB (weight 32)

            unsigned long long m = __ldg(&g_masks[idx]);  // L1-hot broadcast
            unsigned nib = (unsigned)(m >> s) & 0xFu;

            v[i].x = bit_to_1f(nib, 0);
            v[i].y = bit_to_1f(nib, 1);
            v[i].z = bit_to_1f(nib, 2);
            v[i].w = bit_to_1f(nib, 3);
        }
        #pragma unroll
        for (int i = 0; i < 4; i++)
            __stcs(&dst[(g * 4 + i) * 32], v[i]);     // streaming 512B per warp
    }
}

extern "C" void kernel_launch(void* const* d_in, const int* in_sizes, int n_in,
                              void* d_out, int out_size)
{
    const float* table = (const float*)d_in[0];
    const int*   bits  = (const int*)d_in[1];
    float4*      out4  = (float4*)d_out;

    build_masks_kernel<<<2, 1024>>>(table);           // 64 warps, one per row
    spike_lookup_kernel<<<GRID, THREADS>>>(bits, out4);
}